// round 6
// baseline (speedup 1.0000x reference)
#include <cuda_runtime.h>
#include <math.h>
#include <stdint.h>

// Problem constants
#define C_CH 8
#define F_DIM 1024
#define W_FR 512
#define H_HEADS 16
#define D_HEAD 64
#define F4 4096

// ---------------------------------------------------------------------------
// Scratch
// ---------------------------------------------------------------------------
__device__ float g_z[C_CH * F_DIM * W_FR];                       // 16 MB
__device__ float g_p[C_CH * F_DIM * W_FR];                       // 16 MB
__device__ float g_o[C_CH * F_DIM * W_FR];                       // 16 MB
__device__ float g_h[(size_t)C_CH * F4 * W_FR];                  // 64 MB
__device__ float g_s[(size_t)C_CH * H_HEADS * W_FR * W_FR];      // 134 MB

// ---------------------------------------------------------------------------
// Frame norm
// ---------------------------------------------------------------------------
__global__ __launch_bounds__(256) void frame_norm_kernel(
    const float* __restrict__ in, const float* __restrict__ gw,
    const float* __restrict__ bw, float* __restrict__ out)
{
    int c  = blockIdx.x;
    int w0 = blockIdx.y * 32;
    int wx = threadIdx.x & 31;
    int fg = threadIdx.x >> 5;
    const float* base = in + ((size_t)c * F_DIM) * W_FR + w0 + wx;

    float s = 0.f, ss = 0.f;
    for (int f = fg; f < F_DIM; f += 8) {
        float v = base[(size_t)f * W_FR];
        s += v; ss += v * v;
    }
    __shared__ float red[2][8][32];
    __shared__ float smu[32], srs[32];
    red[0][fg][wx] = s; red[1][fg][wx] = ss;
    __syncthreads();
    if (fg == 0) {
        float S = 0.f, SS = 0.f;
#pragma unroll
        for (int i = 0; i < 8; i++) { S += red[0][i][wx]; SS += red[1][i][wx]; }
        float mu  = S * (1.0f / F_DIM);
        float var = SS * (1.0f / F_DIM) - mu * mu;
        smu[wx] = mu;
        srs[wx] = rsqrtf(var + 1e-5f);
    }
    __syncthreads();
    float mu = smu[wx], rs = srs[wx];
    float* ob = out + ((size_t)c * F_DIM) * W_FR + w0 + wx;
    for (int f = fg; f < F_DIM; f += 8) {
        float v = base[(size_t)f * W_FR];
        ob[(size_t)f * W_FR] = (v - mu) * rs * gw[f] + bw[f];
    }
}

// ---------------------------------------------------------------------------
// TF32 tensor-core batched GEMM.
// A: register-prefetch double buffer, SWIZZLED smem layout so each thread's
//    A fragments (k = tig, tig+4, tig+8, tig+12 for rows m, m+8) are single
//    LDS.128s.  pos(k) = (k&3)*4 + (k>>2), quad swizzle Q' = Q ^ ((m>>1)&3).
// B: cp.async 3-stage, row layout [k][BNP].
// 256 threads = 8 warps (2m x 4n), warp tile 64x32, mma m16n8k8 tf32 (RZ).
// epi: 0 = store, 1 = exact GELU, 2 = add residual R
// ---------------------------------------------------------------------------
#define BM 128
#define BN 128
#define BK 16
#define BNP 132

__device__ __forceinline__ void cp16(void* dst, const void* src) {
    uint32_t d = (uint32_t)__cvta_generic_to_shared(dst);
    asm volatile("cp.async.ca.shared.global [%0], [%1], 16;" :: "r"(d), "l"(src));
}

__device__ __forceinline__ void mma_tf32(float* c, const uint32_t* a, const uint32_t* b) {
    asm volatile(
        "mma.sync.aligned.m16n8k8.row.col.f32.tf32.tf32.f32 "
        "{%0,%1,%2,%3}, {%4,%5,%6,%7}, {%8,%9}, {%0,%1,%2,%3};"
        : "+f"(c[0]), "+f"(c[1]), "+f"(c[2]), "+f"(c[3])
        : "r"(a[0]), "r"(a[1]), "r"(a[2]), "r"(a[3]), "r"(b[0]), "r"(b[1]));
}

__global__ __launch_bounds__(256, 2) void tgemm_kernel(
    const float* __restrict__ A, const float* __restrict__ B,
    float* __restrict__ Cm, const float* __restrict__ R,
    int M, int K, int epi)
{
    const int N = W_FR;
    int c  = blockIdx.z;
    int bm = blockIdx.y * BM;
    int bn = blockIdx.x * BN;
    A  += (size_t)c * M * K;
    B  += (size_t)c * K * N;
    Cm += (size_t)c * M * N;
    if (R) R += (size_t)c * M * N;

    __shared__ float As[2][BM][16];      // swizzled, 16 KB
    __shared__ float Bs[3][BK][BNP];     // 25.3 KB

    int tid  = threadIdx.x;
    int warp = tid >> 5;
    int lane = tid & 31;
    int gid  = lane >> 2;
    int tig  = lane & 3;
    int wm   = warp >> 2;
    int wn   = warp & 3;

    // copy assignments
    int am = tid >> 1;             // A row 0..127
    int ak = (tid & 1) * 8;        // A k offset 0/8
    int ao = ak >> 2;              // 0 or 2: offset within quad
    int asw = (am >> 1) & 3;       // store-side swizzle
    int bk = tid >> 4;             // B k row 0..15
    int bc = (tid & 15) * 8;       // B n offset

    const float* Abase = A + (size_t)(bm + am) * K + ak;
    const float* Bbase = B + (size_t)bk * N + bn + bc;

    const int NT = K / BK;

    float ar[8];
    // prologue: A tile 0 -> regs; B tiles 0,1 -> cp.async
    *(float4*)&ar[0] = *(const float4*)(Abase);
    *(float4*)&ar[4] = *(const float4*)(Abase + 4);
    cp16(&Bs[0][bk][bc], Bbase);
    cp16(&Bs[0][bk][bc + 4], Bbase + 4);
    asm volatile("cp.async.commit_group;");
    cp16(&Bs[1][bk][bc], Bbase + (size_t)BK * N);
    cp16(&Bs[1][bk][bc + 4], Bbase + (size_t)BK * N + 4);
    asm volatile("cp.async.commit_group;");
    // store A tile 0 into buffer 0 (swizzled pairs)
#pragma unroll
    for (int j = 0; j < 4; j++)
        *(float2*)&As[0][am][((j ^ asw) << 2) + ao] = make_float2(ar[j], ar[j + 4]);

    float acc[4][4][4];
#pragma unroll
    for (int i = 0; i < 4; i++)
#pragma unroll
        for (int j = 0; j < 4; j++)
#pragma unroll
            for (int q = 0; q < 4; q++) acc[i][j][q] = 0.f;

    int fsw = (gid >> 1) & 3;      // fragment-load swizzle (same for m, m+8)

    for (int t = 0; t < NT; t++) {
        int cura = t & 1;
        int curb = t % 3;
        asm volatile("cp.async.wait_group %0;" :: "n"(1));
        __syncthreads();

        // prefetch A tile t+1 into regs (latency overlapped with compute)
        if (t + 1 < NT) {
            const float* Ap = Abase + (size_t)(t + 1) * BK;
            *(float4*)&ar[0] = *(const float4*)(Ap);
            *(float4*)&ar[4] = *(const float4*)(Ap + 4);
        }

        // B fragments: 16 x LDS.32
        uint32_t bf[4][2][2];
#pragma unroll
        for (int nt = 0; nt < 4; nt++) {
            int nb = wn * 32 + nt * 8 + gid;
#pragma unroll
            for (int kk = 0; kk < 2; kk++) {
                bf[nt][kk][0] = __float_as_uint(Bs[curb][kk * 8 + tig][nb]);
                bf[nt][kk][1] = __float_as_uint(Bs[curb][kk * 8 + tig + 4][nb]);
            }
        }

        // A fragments (LDS.128, both k-halves at once) + mma
#pragma unroll
        for (int mt = 0; mt < 4; mt++) {
            int r0 = wm * 64 + mt * 16 + gid;
            float4 q0 = *(const float4*)&As[cura][r0][(tig ^ fsw) << 2];
            float4 q1 = *(const float4*)&As[cura][r0 + 8][(tig ^ fsw) << 2];
            uint32_t a0[4] = { __float_as_uint(q0.x), __float_as_uint(q1.x),
                               __float_as_uint(q0.y), __float_as_uint(q1.y) };
            uint32_t a1[4] = { __float_as_uint(q0.z), __float_as_uint(q1.z),
                               __float_as_uint(q0.w), __float_as_uint(q1.w) };
#pragma unroll
            for (int nt = 0; nt < 4; nt++) mma_tf32(acc[mt][nt], a0, bf[nt][0]);
#pragma unroll
            for (int nt = 0; nt < 4; nt++) mma_tf32(acc[mt][nt], a1, bf[nt][1]);
        }

        // store A tile t+1 into the other buffer (not being read this iter)
        if (t + 1 < NT) {
#pragma unroll
            for (int j = 0; j < 4; j++)
                *(float2*)&As[cura ^ 1][am][((j ^ asw) << 2) + ao] = make_float2(ar[j], ar[j + 4]);
        }
        // issue B tile t+2 into stage (t+2)%3 (neither read nor pending)
        if (t + 2 < NT) {
            int s2 = (t + 2) % 3;
            const float* Bp = Bbase + (size_t)(t + 2) * BK * N;
            cp16(&Bs[s2][bk][bc], Bp);
            cp16(&Bs[s2][bk][bc + 4], Bp + 4);
        }
        asm volatile("cp.async.commit_group;");
    }

    // epilogue
#pragma unroll
    for (int mt = 0; mt < 4; mt++) {
#pragma unroll
        for (int nt = 0; nt < 4; nt++) {
            int row0 = bm + wm * 64 + mt * 16 + gid;
            int col  = bn + wn * 32 + nt * 8 + 2 * tig;
#pragma unroll
            for (int half = 0; half < 2; half++) {
                int row = row0 + half * 8;
                float2 v = make_float2(acc[mt][nt][half * 2], acc[mt][nt][half * 2 + 1]);
                size_t off = (size_t)row * N + col;
                if (epi == 1) {
                    v.x = 0.5f * v.x * (1.f + erff(v.x * 0.70710678118654752f));
                    v.y = 0.5f * v.y * (1.f + erff(v.y * 0.70710678118654752f));
                } else if (epi == 2) {
                    float2 rv = *(const float2*)(R + off);
                    v.x += rv.x; v.y += rv.y;
                }
                *(float2*)(Cm + off) = v;
            }
        }
    }
}

// ---------------------------------------------------------------------------
// Attention: one block per (c, h). 512 threads = 512 queries.
// ---------------------------------------------------------------------------
#define QS 68
#define VS 36

__global__ __launch_bounds__(512) void attention_kernel(
    const float* __restrict__ p, const float* __restrict__ freqs,
    float* __restrict__ o, float* __restrict__ sbuf)
{
    extern __shared__ float smem[];
    float* qs = smem;               // [512][QS]  roped q (= k); d>=32 also = v
    float* vs = smem + 512 * QS;    // [512][VS]  un-roped first 32 dims (= v)

    int head = blockIdx.x;
    int c = head >> 4;
    int h = head & 15;
    const float* slab = p + ((size_t)c * F_DIM + (size_t)h * D_HEAD) * W_FR;
    int w = threadIdx.x;
    float fw = (float)w;

#pragma unroll
    for (int i = 0; i < 16; i++) {
        float e0 = slab[(size_t)(2 * i) * W_FR + w];
        float e1 = slab[(size_t)(2 * i + 1) * W_FR + w];
        float si, co;
        sincosf(fw * freqs[i], &si, &co);
        qs[w * QS + 2 * i]     = e0 * co - e1 * si;
        qs[w * QS + 2 * i + 1] = e1 * co + e0 * si;
        vs[w * VS + 2 * i]     = e0;
        vs[w * VS + 2 * i + 1] = e1;
    }
#pragma unroll
    for (int d = 32; d < 64; d++)
        qs[w * QS + d] = slab[(size_t)d * W_FR + w];
    __syncthreads();

    float* srow = sbuf + (size_t)head * W_FR * W_FR;
    const float scale = 0.03125f;

    float qi[64];
#pragma unroll
    for (int d = 0; d < 64; d += 4)
        *(float4*)&qi[d] = *(const float4*)&qs[w * QS + d];

    float m = -1e30f, l = 0.f;
    for (int j = 0; j < 512; j++) {
        const float* qj = &qs[j * QS];
        float s0 = 0.f, s1 = 0.f, s2 = 0.f, s3 = 0.f;
#pragma unroll
        for (int d = 0; d < 64; d += 16) {
            float4 a = *(const float4*)&qj[d];
            float4 b = *(const float4*)&qj[d + 4];
            float4 cc = *(const float4*)&qj[d + 8];
            float4 dd = *(const float4*)&qj[d + 12];
            s0 += qi[d] * a.x + qi[d + 1] * a.y + qi[d + 2] * a.z + qi[d + 3] * a.w;
            s1 += qi[d + 4] * b.x + qi[d + 5] * b.y + qi[d + 6] * b.z + qi[d + 7] * b.w;
            s2 += qi[d + 8] * cc.x + qi[d + 9] * cc.y + qi[d + 10] * cc.z + qi[d + 11] * cc.w;
            s3 += qi[d + 12] * dd.x + qi[d + 13] * dd.y + qi[d + 14] * dd.z + qi[d + 15] * dd.w;
        }
        float s = ((s0 + s1) + (s2 + s3)) * scale;
        srow[(size_t)j * W_FR + w] = s;
        float mn = fmaxf(m, s);
        l = l * __expf(m - mn) + __expf(s - mn);
        m = mn;
    }
    float linv = 1.f / l;

    float oa[64];
#pragma unroll
    for (int d = 0; d < 64; d++) oa[d] = 0.f;

    for (int j = 0; j < 512; j++) {
        float pij = __expf(srow[(size_t)j * W_FR + w] - m) * linv;
        const float* vj = &vs[j * VS];
        const float* qj = &qs[j * QS];
#pragma unroll
        for (int d = 0; d < 32; d += 4) {
            float4 v4 = *(const float4*)&vj[d];
            oa[d]     += pij * v4.x;
            oa[d + 1] += pij * v4.y;
            oa[d + 2] += pij * v4.z;
            oa[d + 3] += pij * v4.w;
        }
#pragma unroll
        for (int d = 32; d < 64; d += 4) {
            float4 v4 = *(const float4*)&qj[d];
            oa[d]     += pij * v4.x;
            oa[d + 1] += pij * v4.y;
            oa[d + 2] += pij * v4.z;
            oa[d + 3] += pij * v4.w;
        }
    }

    float* ob = o + ((size_t)c * F_DIM + (size_t)h * D_HEAD) * W_FR + w;
#pragma unroll
    for (int d = 0; d < 64; d++)
        ob[(size_t)d * W_FR] = oa[d];
}

// ---------------------------------------------------------------------------
// Launch
// ---------------------------------------------------------------------------
extern "C" void kernel_launch(void* const* d_in, const int* in_sizes, int n_in,
                              void* d_out, int out_size)
{
    (void)in_sizes; (void)n_in; (void)out_size;
    const float* x  = (const float*)d_in[0];
    const float* g1 = (const float*)d_in[1];
    const float* b1 = (const float*)d_in[2];
    const float* wq = (const float*)d_in[3];
    const float* wo = (const float*)d_in[4];
    const float* fr = (const float*)d_in[5];
    const float* g2 = (const float*)d_in[6];
    const float* b2 = (const float*)d_in[7];
    const float* w1 = (const float*)d_in[8];
    const float* w2 = (const float*)d_in[9];
    float* out = (float*)d_out;

    float *z, *p, *o, *h, *s;
    cudaGetSymbolAddress((void**)&z, g_z);
    cudaGetSymbolAddress((void**)&p, g_p);
    cudaGetSymbolAddress((void**)&o, g_o);
    cudaGetSymbolAddress((void**)&h, g_h);
    cudaGetSymbolAddress((void**)&s, g_s);

    int smem_attn = 512 * (QS + VS) * (int)sizeof(float);
    cudaFuncSetAttribute(attention_kernel,
                         cudaFuncAttributeMaxDynamicSharedMemorySize, smem_attn);

    // z = frame_norm(x)
    frame_norm_kernel<<<dim3(8, 16), 256>>>(x, g1, b1, z);
    // p = w_q @ z
    tgemm_kernel<<<dim3(4, 8, 8), 256>>>(wq, z, p, nullptr, F_DIM, F_DIM, 0);
    // o = attention(p)
    attention_kernel<<<128, 512, smem_attn>>>(p, fr, o, s);
    // x2 = x + w_o @ o   -> d_out
    tgemm_kernel<<<dim3(4, 8, 8), 256>>>(wo, o, out, x, F_DIM, F_DIM, 2);
    // z2 = frame_norm(x2)
    frame_norm_kernel<<<dim3(8, 16), 256>>>(out, g2, b2, z);
    // hgelu = gelu(w1 @ z2)
    tgemm_kernel<<<dim3(4, 32, 8), 256>>>(w1, z, h, nullptr, F4, F_DIM, 1);
    // out = x2 + w2 @ hgelu
    tgemm_kernel<<<dim3(4, 8, 8), 256>>>(w2, h, out, out, F_DIM, F4, 2);
}

// round 8
// speedup vs baseline: 1.2769x; 1.2769x over previous
#include <cuda_runtime.h>
#include <cuda_fp16.h>
#include <math.h>
#include <stdint.h>

// Problem constants
#define C_CH 8
#define F_DIM 1024
#define W_FR 512
#define H_HEADS 16
#define D_HEAD 64
#define F4 4096

// ---------------------------------------------------------------------------
// Scratch
// ---------------------------------------------------------------------------
__device__ float g_z[C_CH * F_DIM * W_FR];                        // 16 MB
__device__ float g_p[C_CH * F_DIM * W_FR];                        // 16 MB
__device__ float g_o[C_CH * F_DIM * W_FR];                        // 16 MB
__device__ float g_h[(size_t)C_CH * F4 * W_FR];                   // 64 MB
__device__ float g_s[(size_t)C_CH * H_HEADS * W_FR * W_FR];       // 134 MB scores
__device__ __align__(16) __half g_wqh[C_CH * F_DIM * F_DIM];      // 16 MB
__device__ __align__(16) __half g_woh[C_CH * F_DIM * F_DIM];      // 16 MB
__device__ __align__(16) __half g_w1h[(size_t)C_CH * F4 * F_DIM]; // 64 MB
__device__ __align__(16) __half g_w2h[(size_t)C_CH * F_DIM * F4]; // 64 MB
__device__ __align__(16) __half g_t1h[C_CH * W_FR * F_DIM];       // 8 MB  acts^T fp16
__device__ __align__(16) __half g_t2h[(size_t)C_CH * W_FR * F4];  // 32 MB hidden^T fp16

// ---------------------------------------------------------------------------
// fp32 -> fp16 elementwise (weights), 4 elems/thread
// ---------------------------------------------------------------------------
__global__ __launch_bounds__(256) void f2h_kernel(
    const float* __restrict__ in, __half* __restrict__ out, size_t n)
{
    size_t i = ((size_t)blockIdx.x * blockDim.x + threadIdx.x) * 4;
    if (i >= n) return;
    float4 v = *(const float4*)(in + i);
    *(__half2*)(out + i)     = __floats2half2_rn(v.x, v.y);
    *(__half2*)(out + i + 2) = __floats2half2_rn(v.z, v.w);
}

// ---------------------------------------------------------------------------
// Transpose + convert: out_h[c][n][k] = (half) in[c][k][n]
// grid (K/32, N/32, C), block (32, 8)
// ---------------------------------------------------------------------------
__global__ __launch_bounds__(256) void tch_kernel(
    const float* __restrict__ in, __half* __restrict__ out, int K, int N)
{
    __shared__ float t[32][33];
    int c  = blockIdx.z;
    int k0 = blockIdx.x * 32, n0 = blockIdx.y * 32;
    in  += (size_t)c * K * N;
    out += (size_t)c * N * K;
    int tx = threadIdx.x, ty = threadIdx.y;
#pragma unroll
    for (int j = 0; j < 32; j += 8)
        t[ty + j][tx] = in[(size_t)(k0 + ty + j) * N + n0 + tx];
    __syncthreads();
#pragma unroll
    for (int j = 0; j < 32; j += 8)
        out[(size_t)(n0 + ty + j) * K + k0 + tx] = __float2half(t[tx][ty + j]);
}

// ---------------------------------------------------------------------------
// Frame norm (unchanged)
// ---------------------------------------------------------------------------
__global__ __launch_bounds__(256) void frame_norm_kernel(
    const float* __restrict__ in, const float* __restrict__ gw,
    const float* __restrict__ bw, float* __restrict__ out)
{
    int c  = blockIdx.x;
    int w0 = blockIdx.y * 32;
    int wx = threadIdx.x & 31;
    int fg = threadIdx.x >> 5;
    const float* base = in + ((size_t)c * F_DIM) * W_FR + w0 + wx;

    float s = 0.f, ss = 0.f;
    for (int f = fg; f < F_DIM; f += 8) {
        float v = base[(size_t)f * W_FR];
        s += v; ss += v * v;
    }
    __shared__ float red[2][8][32];
    __shared__ float smu[32], srs[32];
    red[0][fg][wx] = s; red[1][fg][wx] = ss;
    __syncthreads();
    if (fg == 0) {
        float S = 0.f, SS = 0.f;
#pragma unroll
        for (int i = 0; i < 8; i++) { S += red[0][i][wx]; SS += red[1][i][wx]; }
        float mu  = S * (1.0f / F_DIM);
        float var = SS * (1.0f / F_DIM) - mu * mu;
        smu[wx] = mu;
        srs[wx] = rsqrtf(var + 1e-5f);
    }
    __syncthreads();
    float mu = smu[wx], rs = srs[wx];
    float* ob = out + ((size_t)c * F_DIM) * W_FR + w0 + wx;
    for (int f = fg; f < F_DIM; f += 8) {
        float v = base[(size_t)f * W_FR];
        ob[(size_t)f * W_FR] = (v - mu) * rs * gw[f] + bw[f];
    }
}

// ---------------------------------------------------------------------------
// FP16 tensor-core batched GEMM (mma.sync.m16n8k16.f16, fp32 accum)
// C[c][M,512] = A[c][M,K] (row-major fp16) x BT[c][512,K] (row-major fp16).
// Both operands K-major: every fragment is a contiguous half2 -> LDS.32.
// Tile 128x128x16, 3-stage cp.async, 256 thr = 8 warps (2m x 4n).
// Smem rows padded to 24 halves (48B): fragment phases hit 32 distinct banks.
// epi: 0 = store, 1 = exact GELU, 2 = add residual R
// ---------------------------------------------------------------------------
#define BKH 16
#define HPAD 24

__device__ __forceinline__ void cp16(void* dst, const void* src) {
    uint32_t d = (uint32_t)__cvta_generic_to_shared(dst);
    asm volatile("cp.async.ca.shared.global [%0], [%1], 16;" :: "r"(d), "l"(src));
}

__device__ __forceinline__ void mma_f16(float* c, const uint32_t* a, const uint32_t* b) {
    asm volatile(
        "mma.sync.aligned.m16n8k16.row.col.f32.f16.f16.f32 "
        "{%0,%1,%2,%3}, {%4,%5,%6,%7}, {%8,%9}, {%0,%1,%2,%3};"
        : "+f"(c[0]), "+f"(c[1]), "+f"(c[2]), "+f"(c[3])
        : "r"(a[0]), "r"(a[1]), "r"(a[2]), "r"(a[3]), "r"(b[0]), "r"(b[1]));
}

__global__ __launch_bounds__(256, 2) void hgemm_kernel(
    const __half* __restrict__ A, const __half* __restrict__ BT,
    float* __restrict__ Cm, const float* __restrict__ R,
    int M, int K, int epi)
{
    const int N = W_FR;
    int c  = blockIdx.z;
    int bm = blockIdx.y * 128;
    int bn = blockIdx.x * 128;
    A  += (size_t)c * M * K;
    BT += (size_t)c * N * K;
    Cm += (size_t)c * M * N;
    if (R) R += (size_t)c * M * N;

    __shared__ __half As[3][128 * HPAD];   // 18 KB
    __shared__ __half Bs[3][128 * HPAD];   // 18 KB

    int tid  = threadIdx.x;
    int warp = tid >> 5;
    int lane = tid & 31;
    int gid  = lane >> 2;
    int tig  = lane & 3;
    int wm   = warp >> 2;
    int wn   = warp & 3;

    // copy assignment: row = tid>>1 (0..127), chunk = tid&1 (16B halves 0..7 / 8..15)
    int cr = tid >> 1;
    int cc = tid & 1;
    const __half* Ag = A  + (size_t)(bm + cr) * K + cc * 8;
    const __half* Bg = BT + (size_t)(bn + cr) * K + cc * 8;
    int sdst = cr * HPAD + cc * 8;

    const int NT = K / BKH;

    // prologue: stages 0, 1
#pragma unroll
    for (int t = 0; t < 2; t++) {
        cp16(&As[t][sdst], Ag + (size_t)t * BKH);
        cp16(&Bs[t][sdst], Bg + (size_t)t * BKH);
        asm volatile("cp.async.commit_group;");
    }

    float acc[4][4][4];
#pragma unroll
    for (int i = 0; i < 4; i++)
#pragma unroll
        for (int j = 0; j < 4; j++)
#pragma unroll
            for (int q = 0; q < 4; q++) acc[i][j][q] = 0.f;

    for (int t = 0; t < NT; t++) {
        int cur = t % 3;
        asm volatile("cp.async.wait_group %0;" :: "n"(1));
        __syncthreads();

        // B fragments: 8 x LDS.32
        uint32_t bf[4][2];
#pragma unroll
        for (int nt = 0; nt < 4; nt++) {
            int nb = (wn * 32 + nt * 8 + gid) * HPAD + 2 * tig;
            bf[nt][0] = *(const uint32_t*)&Bs[cur][nb];
            bf[nt][1] = *(const uint32_t*)&Bs[cur][nb + 8];
        }

        // A fragments (16 x LDS.32) + mma
#pragma unroll
        for (int mt = 0; mt < 4; mt++) {
            int r0 = (wm * 64 + mt * 16 + gid) * HPAD + 2 * tig;
            int r1 = r0 + 8 * HPAD;
            uint32_t af[4];
            af[0] = *(const uint32_t*)&As[cur][r0];
            af[1] = *(const uint32_t*)&As[cur][r1];
            af[2] = *(const uint32_t*)&As[cur][r0 + 8];
            af[3] = *(const uint32_t*)&As[cur][r1 + 8];
#pragma unroll
            for (int nt = 0; nt < 4; nt++) mma_f16(acc[mt][nt], af, bf[nt]);
        }

        // issue tile t+2 into stage (t+2)%3 (synced above: no reader)
        if (t + 2 < NT) {
            int s2 = (t + 2) % 3;
            cp16(&As[s2][sdst], Ag + (size_t)(t + 2) * BKH);
            cp16(&Bs[s2][sdst], Bg + (size_t)(t + 2) * BKH);
        }
        asm volatile("cp.async.commit_group;");
    }

    // epilogue
#pragma unroll
    for (int mt = 0; mt < 4; mt++) {
#pragma unroll
        for (int nt = 0; nt < 4; nt++) {
            int row0 = bm + wm * 64 + mt * 16 + gid;
            int col  = bn + wn * 32 + nt * 8 + 2 * tig;
#pragma unroll
            for (int half = 0; half < 2; half++) {
                int row = row0 + half * 8;
                float2 v = make_float2(acc[mt][nt][half * 2], acc[mt][nt][half * 2 + 1]);
                size_t off = (size_t)row * N + col;
                if (epi == 1) {
                    v.x = 0.5f * v.x * (1.f + erff(v.x * 0.70710678118654752f));
                    v.y = 0.5f * v.y * (1.f + erff(v.y * 0.70710678118654752f));
                } else if (epi == 2) {
                    float2 rv = *(const float2*)(R + off);
                    v.x += rv.x; v.y += rv.y;
                }
                *(float2*)(Cm + off) = v;
            }
        }
    }
}

// ---------------------------------------------------------------------------
// Attention (unchanged): one block per (c, h). 512 threads = 512 queries.
// ---------------------------------------------------------------------------
#define QS 68
#define VS 36

__global__ __launch_bounds__(512) void attention_kernel(
    const float* __restrict__ p, const float* __restrict__ freqs,
    float* __restrict__ o, float* __restrict__ sbuf)
{
    extern __shared__ float smem[];
    float* qs = smem;
    float* vs = smem + 512 * QS;

    int head = blockIdx.x;
    int c = head >> 4;
    int h = head & 15;
    const float* slab = p + ((size_t)c * F_DIM + (size_t)h * D_HEAD) * W_FR;
    int w = threadIdx.x;
    float fw = (float)w;

#pragma unroll
    for (int i = 0; i < 16; i++) {
        float e0 = slab[(size_t)(2 * i) * W_FR + w];
        float e1 = slab[(size_t)(2 * i + 1) * W_FR + w];
        float si, co;
        sincosf(fw * freqs[i], &si, &co);
        qs[w * QS + 2 * i]     = e0 * co - e1 * si;
        qs[w * QS + 2 * i + 1] = e1 * co + e0 * si;
        vs[w * VS + 2 * i]     = e0;
        vs[w * VS + 2 * i + 1] = e1;
    }
#pragma unroll
    for (int d = 32; d < 64; d++)
        qs[w * QS + d] = slab[(size_t)d * W_FR + w];
    __syncthreads();

    float* srow = sbuf + (size_t)head * W_FR * W_FR;
    const float scale = 0.03125f;

    float qi[64];
#pragma unroll
    for (int d = 0; d < 64; d += 4)
        *(float4*)&qi[d] = *(const float4*)&qs[w * QS + d];

    float m = -1e30f, l = 0.f;
    for (int j = 0; j < 512; j++) {
        const float* qj = &qs[j * QS];
        float s0 = 0.f, s1 = 0.f, s2 = 0.f, s3 = 0.f;
#pragma unroll
        for (int d = 0; d < 64; d += 16) {
            float4 a = *(const float4*)&qj[d];
            float4 b = *(const float4*)&qj[d + 4];
            float4 cc = *(const float4*)&qj[d + 8];
            float4 dd = *(const float4*)&qj[d + 12];
            s0 += qi[d] * a.x + qi[d + 1] * a.y + qi[d + 2] * a.z + qi[d + 3] * a.w;
            s1 += qi[d + 4] * b.x + qi[d + 5] * b.y + qi[d + 6] * b.z + qi[d + 7] * b.w;
            s2 += qi[d + 8] * cc.x + qi[d + 9] * cc.y + qi[d + 10] * cc.z + qi[d + 11] * cc.w;
            s3 += qi[d + 12] * dd.x + qi[d + 13] * dd.y + qi[d + 14] * dd.z + qi[d + 15] * dd.w;
        }
        float s = ((s0 + s1) + (s2 + s3)) * scale;
        srow[(size_t)j * W_FR + w] = s;
        float mn = fmaxf(m, s);
        l = l * __expf(m - mn) + __expf(s - mn);
        m = mn;
    }
    float linv = 1.f / l;

    float oa[64];
#pragma unroll
    for (int d = 0; d < 64; d++) oa[d] = 0.f;

    for (int j = 0; j < 512; j++) {
        float pij = __expf(srow[(size_t)j * W_FR + w] - m) * linv;
        const float* vj = &vs[j * VS];
        const float* qj = &qs[j * QS];
#pragma unroll
        for (int d = 0; d < 32; d += 4) {
            float4 v4 = *(const float4*)&vj[d];
            oa[d]     += pij * v4.x;
            oa[d + 1] += pij * v4.y;
            oa[d + 2] += pij * v4.z;
            oa[d + 3] += pij * v4.w;
        }
#pragma unroll
        for (int d = 32; d < 64; d += 4) {
            float4 v4 = *(const float4*)&qj[d];
            oa[d]     += pij * v4.x;
            oa[d + 1] += pij * v4.y;
            oa[d + 2] += pij * v4.z;
            oa[d + 3] += pij * v4.w;
        }
    }

    float* ob = o + ((size_t)c * F_DIM + (size_t)h * D_HEAD) * W_FR + w;
#pragma unroll
    for (int d = 0; d < 64; d++)
        ob[(size_t)d * W_FR] = oa[d];
}

// ---------------------------------------------------------------------------
// Launch
// ---------------------------------------------------------------------------
extern "C" void kernel_launch(void* const* d_in, const int* in_sizes, int n_in,
                              void* d_out, int out_size)
{
    (void)in_sizes; (void)n_in; (void)out_size;
    const float* x  = (const float*)d_in[0];
    const float* g1 = (const float*)d_in[1];
    const float* b1 = (const float*)d_in[2];
    const float* wq = (const float*)d_in[3];
    const float* wo = (const float*)d_in[4];
    const float* fr = (const float*)d_in[5];
    const float* g2 = (const float*)d_in[6];
    const float* b2 = (const float*)d_in[7];
    const float* w1 = (const float*)d_in[8];
    const float* w2 = (const float*)d_in[9];
    float* out = (float*)d_out;

    float *z, *p, *o, *h, *s;
    __half *wqh, *woh, *w1h, *w2h, *t1h, *t2h;
    cudaGetSymbolAddress((void**)&z,   g_z);
    cudaGetSymbolAddress((void**)&p,   g_p);
    cudaGetSymbolAddress((void**)&o,   g_o);
    cudaGetSymbolAddress((void**)&h,   g_h);
    cudaGetSymbolAddress((void**)&s,   g_s);
    cudaGetSymbolAddress((void**)&wqh, g_wqh);
    cudaGetSymbolAddress((void**)&woh, g_woh);
    cudaGetSymbolAddress((void**)&w1h, g_w1h);
    cudaGetSymbolAddress((void**)&w2h, g_w2h);
    cudaGetSymbolAddress((void**)&t1h, g_t1h);
    cudaGetSymbolAddress((void**)&t2h, g_t2h);

    int smem_attn = 512 * (QS + VS) * (int)sizeof(float);
    cudaFuncSetAttribute(attention_kernel,
                         cudaFuncAttributeMaxDynamicSharedMemorySize, smem_attn);

    const size_t nw  = (size_t)C_CH * F_DIM * F_DIM;    // 8M
    const size_t nw1 = (size_t)C_CH * F4 * F_DIM;       // 32M
    dim3 tb(32, 8);

    // weight conversions (fp32 -> fp16)
    f2h_kernel<<<(int)(nw  / 4 / 256), 256>>>(wq, wqh, nw);
    f2h_kernel<<<(int)(nw  / 4 / 256), 256>>>(wo, woh, nw);
    f2h_kernel<<<(int)(nw1 / 4 / 256), 256>>>(w1, w1h, nw1);
    f2h_kernel<<<(int)(nw1 / 4 / 256), 256>>>(w2, w2h, nw1);

    // z = frame_norm(x); t1h = (half) z^T
    frame_norm_kernel<<<dim3(8, 16), 256>>>(x, g1, b1, z);
    tch_kernel<<<dim3(32, 16, 8), tb>>>(z, t1h, F_DIM, W_FR);
    // p = w_q @ z
    hgemm_kernel<<<dim3(4, 8, 8), 256>>>(wqh, t1h, p, nullptr, F_DIM, F_DIM, 0);
    // o = attention(p)
    attention_kernel<<<128, 512, smem_attn>>>(p, fr, o, s);
    // t1h = (half) o^T ; out = x + w_o @ o
    tch_kernel<<<dim3(32, 16, 8), tb>>>(o, t1h, F_DIM, W_FR);
    hgemm_kernel<<<dim3(4, 8, 8), 256>>>(woh, t1h, out, x, F_DIM, F_DIM, 2);
    // z = frame_norm(out); t1h = (half) z^T
    frame_norm_kernel<<<dim3(8, 16), 256>>>(out, g2, b2, z);
    tch_kernel<<<dim3(32, 16, 8), tb>>>(z, t1h, F_DIM, W_FR);
    // h = gelu(w1 @ z)
    hgemm_kernel<<<dim3(4, 32, 8), 256>>>(w1h, t1h, h, nullptr, F4, F_DIM, 1);
    // t2h = (half) h^T ; out = out + w2 @ h
    tch_kernel<<<dim3(128, 16, 8), tb>>>(h, t2h, F4, W_FR);
    hgemm_kernel<<<dim3(4, 8, 8), 256>>>(w2h, t2h, out, out, F_DIM, F4, 2);
}

// round 9
// speedup vs baseline: 1.9871x; 1.5562x over previous
#include <cuda_runtime.h>
#include <cuda_fp16.h>
#include <math.h>
#include <stdint.h>

// Problem constants
#define C_CH 8
#define F_DIM 1024
#define W_FR 512
#define H_HEADS 16
#define D_HEAD 64
#define F4 4096

// ---------------------------------------------------------------------------
// Scratch
// ---------------------------------------------------------------------------
__device__ float g_z[C_CH * F_DIM * W_FR];                        // 16 MB
__device__ float g_p[C_CH * F_DIM * W_FR];                        // 16 MB
__device__ float g_o[C_CH * F_DIM * W_FR];                        // 16 MB
__device__ float g_h[(size_t)C_CH * F4 * W_FR];                   // 64 MB
__device__ __align__(16) __half g_wqh[C_CH * F_DIM * F_DIM];      // 16 MB
__device__ __align__(16) __half g_woh[C_CH * F_DIM * F_DIM];      // 16 MB
__device__ __align__(16) __half g_w1h[(size_t)C_CH * F4 * F_DIM]; // 64 MB
__device__ __align__(16) __half g_w2h[(size_t)C_CH * F_DIM * F4]; // 64 MB
__device__ __align__(16) __half g_t1h[C_CH * W_FR * F_DIM];       // 8 MB
__device__ __align__(16) __half g_t2h[(size_t)C_CH * W_FR * F4];  // 32 MB

// ---------------------------------------------------------------------------
// fp32 -> fp16 elementwise (weights)
// ---------------------------------------------------------------------------
__global__ __launch_bounds__(256) void f2h_kernel(
    const float* __restrict__ in, __half* __restrict__ out, size_t n)
{
    size_t i = ((size_t)blockIdx.x * blockDim.x + threadIdx.x) * 4;
    if (i >= n) return;
    float4 v = *(const float4*)(in + i);
    *(__half2*)(out + i)     = __floats2half2_rn(v.x, v.y);
    *(__half2*)(out + i + 2) = __floats2half2_rn(v.z, v.w);
}

// ---------------------------------------------------------------------------
// Transpose + convert: out_h[c][n][k] = (half) in[c][k][n]
// ---------------------------------------------------------------------------
__global__ __launch_bounds__(256) void tch_kernel(
    const float* __restrict__ in, __half* __restrict__ out, int K, int N)
{
    __shared__ float t[32][33];
    int c  = blockIdx.z;
    int k0 = blockIdx.x * 32, n0 = blockIdx.y * 32;
    in  += (size_t)c * K * N;
    out += (size_t)c * N * K;
    int tx = threadIdx.x, ty = threadIdx.y;
#pragma unroll
    for (int j = 0; j < 32; j += 8)
        t[ty + j][tx] = in[(size_t)(k0 + ty + j) * N + n0 + tx];
    __syncthreads();
#pragma unroll
    for (int j = 0; j < 32; j += 8)
        out[(size_t)(n0 + ty + j) * K + k0 + tx] = __float2half(t[tx][ty + j]);
}

// ---------------------------------------------------------------------------
// Frame norm (unchanged)
// ---------------------------------------------------------------------------
__global__ __launch_bounds__(256) void frame_norm_kernel(
    const float* __restrict__ in, const float* __restrict__ gw,
    const float* __restrict__ bw, float* __restrict__ out)
{
    int c  = blockIdx.x;
    int w0 = blockIdx.y * 32;
    int wx = threadIdx.x & 31;
    int fg = threadIdx.x >> 5;
    const float* base = in + ((size_t)c * F_DIM) * W_FR + w0 + wx;

    float s = 0.f, ss = 0.f;
    for (int f = fg; f < F_DIM; f += 8) {
        float v = base[(size_t)f * W_FR];
        s += v; ss += v * v;
    }
    __shared__ float red[2][8][32];
    __shared__ float smu[32], srs[32];
    red[0][fg][wx] = s; red[1][fg][wx] = ss;
    __syncthreads();
    if (fg == 0) {
        float S = 0.f, SS = 0.f;
#pragma unroll
        for (int i = 0; i < 8; i++) { S += red[0][i][wx]; SS += red[1][i][wx]; }
        float mu  = S * (1.0f / F_DIM);
        float var = SS * (1.0f / F_DIM) - mu * mu;
        smu[wx] = mu;
        srs[wx] = rsqrtf(var + 1e-5f);
    }
    __syncthreads();
    float mu = smu[wx], rs = srs[wx];
    float* ob = out + ((size_t)c * F_DIM) * W_FR + w0 + wx;
    for (int f = fg; f < F_DIM; f += 8) {
        float v = base[(size_t)f * W_FR];
        ob[(size_t)f * W_FR] = (v - mu) * rs * gw[f] + bw[f];
    }
}

// ---------------------------------------------------------------------------
// mma helpers
// ---------------------------------------------------------------------------
__device__ __forceinline__ void cp16(void* dst, const void* src) {
    uint32_t d = (uint32_t)__cvta_generic_to_shared(dst);
    asm volatile("cp.async.ca.shared.global [%0], [%1], 16;" :: "r"(d), "l"(src));
}
__device__ __forceinline__ void mma_f16(float* c, const uint32_t* a, const uint32_t* b) {
    asm volatile(
        "mma.sync.aligned.m16n8k16.row.col.f32.f16.f16.f32 "
        "{%0,%1,%2,%3}, {%4,%5,%6,%7}, {%8,%9}, {%0,%1,%2,%3};"
        : "+f"(c[0]), "+f"(c[1]), "+f"(c[2]), "+f"(c[3])
        : "r"(a[0]), "r"(a[1]), "r"(a[2]), "r"(a[3]), "r"(b[0]), "r"(b[1]));
}

// ---------------------------------------------------------------------------
// FP16 tensor-core batched GEMM (unchanged from R8)
// ---------------------------------------------------------------------------
#define BKH 16
#define HPAD 24

__global__ __launch_bounds__(256, 2) void hgemm_kernel(
    const __half* __restrict__ A, const __half* __restrict__ BT,
    float* __restrict__ Cm, const float* __restrict__ R,
    int M, int K, int epi)
{
    const int N = W_FR;
    int c  = blockIdx.z;
    int bm = blockIdx.y * 128;
    int bn = blockIdx.x * 128;
    A  += (size_t)c * M * K;
    BT += (size_t)c * N * K;
    Cm += (size_t)c * M * N;
    if (R) R += (size_t)c * M * N;

    __shared__ __half As[3][128 * HPAD];
    __shared__ __half Bs[3][128 * HPAD];

    int tid  = threadIdx.x;
    int warp = tid >> 5;
    int lane = tid & 31;
    int gid  = lane >> 2;
    int tig  = lane & 3;
    int wm   = warp >> 2;
    int wn   = warp & 3;

    int cr = tid >> 1;
    int cc = tid & 1;
    const __half* Ag = A  + (size_t)(bm + cr) * K + cc * 8;
    const __half* Bg = BT + (size_t)(bn + cr) * K + cc * 8;
    int sdst = cr * HPAD + cc * 8;

    const int NT = K / BKH;

#pragma unroll
    for (int t = 0; t < 2; t++) {
        cp16(&As[t][sdst], Ag + (size_t)t * BKH);
        cp16(&Bs[t][sdst], Bg + (size_t)t * BKH);
        asm volatile("cp.async.commit_group;");
    }

    float acc[4][4][4];
#pragma unroll
    for (int i = 0; i < 4; i++)
#pragma unroll
        for (int j = 0; j < 4; j++)
#pragma unroll
            for (int q = 0; q < 4; q++) acc[i][j][q] = 0.f;

    for (int t = 0; t < NT; t++) {
        int cur = t % 3;
        asm volatile("cp.async.wait_group %0;" :: "n"(1));
        __syncthreads();

        uint32_t bf[4][2];
#pragma unroll
        for (int nt = 0; nt < 4; nt++) {
            int nb = (wn * 32 + nt * 8 + gid) * HPAD + 2 * tig;
            bf[nt][0] = *(const uint32_t*)&Bs[cur][nb];
            bf[nt][1] = *(const uint32_t*)&Bs[cur][nb + 8];
        }

#pragma unroll
        for (int mt = 0; mt < 4; mt++) {
            int r0 = (wm * 64 + mt * 16 + gid) * HPAD + 2 * tig;
            int r1 = r0 + 8 * HPAD;
            uint32_t af[4];
            af[0] = *(const uint32_t*)&As[cur][r0];
            af[1] = *(const uint32_t*)&As[cur][r1];
            af[2] = *(const uint32_t*)&As[cur][r0 + 8];
            af[3] = *(const uint32_t*)&As[cur][r1 + 8];
#pragma unroll
            for (int nt = 0; nt < 4; nt++) mma_f16(acc[mt][nt], af, bf[nt]);
        }

        if (t + 2 < NT) {
            int s2 = (t + 2) % 3;
            cp16(&As[s2][sdst], Ag + (size_t)(t + 2) * BKH);
            cp16(&Bs[s2][sdst], Bg + (size_t)(t + 2) * BKH);
        }
        asm volatile("cp.async.commit_group;");
    }

#pragma unroll
    for (int mt = 0; mt < 4; mt++) {
#pragma unroll
        for (int nt = 0; nt < 4; nt++) {
            int row0 = bm + wm * 64 + mt * 16 + gid;
            int col  = bn + wn * 32 + nt * 8 + 2 * tig;
#pragma unroll
            for (int half = 0; half < 2; half++) {
                int row = row0 + half * 8;
                float2 v = make_float2(acc[mt][nt][half * 2], acc[mt][nt][half * 2 + 1]);
                size_t off = (size_t)row * N + col;
                if (epi == 1) {
                    v.x = 0.5f * v.x * (1.f + erff(v.x * 0.70710678118654752f));
                    v.y = 0.5f * v.y * (1.f + erff(v.y * 0.70710678118654752f));
                } else if (epi == 2) {
                    float2 rv = *(const float2*)(R + off);
                    v.x += rv.x; v.y += rv.y;
                }
                *(float2*)(Cm + off) = v;
            }
        }
    }
}

// ---------------------------------------------------------------------------
// Flash attention, fp16 mma. Grid = 256 (128 heads x 2 q-halves), 256 thr.
// smem: qk[512][AQS] fp16 (roped q=k; d>=32 also = v) + vs[64][AVS] fp16
// (full v, d-major). 8 warps x 32 queries; online softmax over 8 chunks of
// 64 keys; S-frags become P A-frags in registers. O transposed via reused
// smem for coalesced [d][w] stores.
// ---------------------------------------------------------------------------
#define AQS 72
#define AVS 520
#define ATT_SMEM (512 * AQS * 2 + 64 * AVS * 2)   // 140,288 B

__global__ __launch_bounds__(256) void fattn_kernel(
    const float* __restrict__ p, const float* __restrict__ freqs,
    float* __restrict__ o)
{
    extern __shared__ __align__(16) char smraw[];
    __half* qk = (__half*)smraw;
    __half* vs = (__half*)(smraw + 512 * AQS * 2);

    int head = blockIdx.x >> 1;
    int qh   = blockIdx.x & 1;
    int c  = head >> 4;
    int hh = head & 15;
    const float* slab = p + ((size_t)c * F_DIM + (size_t)hh * D_HEAD) * W_FR;

    int tid = threadIdx.x;

    // ---- load + rope + convert (whole head: 512 keys) ----
#pragma unroll
    for (int rep = 0; rep < 2; rep++) {
        int w = tid + rep * 256;
        float fw = (float)w;
#pragma unroll
        for (int i = 0; i < 16; i++) {
            float e0 = slab[(size_t)(2 * i) * W_FR + w];
            float e1 = slab[(size_t)(2 * i + 1) * W_FR + w];
            float si, co;
            sincosf(fw * freqs[i], &si, &co);
            qk[w * AQS + 2 * i]     = __float2half(e0 * co - e1 * si);
            qk[w * AQS + 2 * i + 1] = __float2half(e1 * co + e0 * si);
            vs[(2 * i) * AVS + w]     = __float2half(e0);
            vs[(2 * i + 1) * AVS + w] = __float2half(e1);
        }
#pragma unroll
        for (int d = 32; d < 64; d++) {
            __half he = __float2half(slab[(size_t)d * W_FR + w]);
            qk[w * AQS + d] = he;
            vs[d * AVS + w] = he;
        }
    }
    __syncthreads();

    int warp = tid >> 5, lane = tid & 31, gid = lane >> 2, tig = lane & 3;
    int q0 = qh * 256 + warp * 32;
    const float scale = 0.03125f;    // 1/sqrt(F)

    // resident Q fragments
    uint32_t qf[2][4][4];
#pragma unroll
    for (int mt = 0; mt < 2; mt++) {
        int qr = q0 + mt * 16 + gid;
#pragma unroll
        for (int ks = 0; ks < 4; ks++) {
            int kb = 16 * ks + 2 * tig;
            qf[mt][ks][0] = *(const uint32_t*)&qk[qr * AQS + kb];
            qf[mt][ks][1] = *(const uint32_t*)&qk[(qr + 8) * AQS + kb];
            qf[mt][ks][2] = *(const uint32_t*)&qk[qr * AQS + kb + 8];
            qf[mt][ks][3] = *(const uint32_t*)&qk[(qr + 8) * AQS + kb + 8];
        }
    }

    float oacc[2][8][4];
#pragma unroll
    for (int mt = 0; mt < 2; mt++)
#pragma unroll
        for (int nt = 0; nt < 8; nt++)
#pragma unroll
            for (int q = 0; q < 4; q++) oacc[mt][nt][q] = 0.f;
    float mrow[2][2] = { {-1e30f, -1e30f}, {-1e30f, -1e30f} };
    float lrow[2][2] = { {0.f, 0.f}, {0.f, 0.f} };

    for (int ch = 0; ch < 8; ch++) {
        int cb = ch * 64;
        float sacc[2][8][4];
#pragma unroll
        for (int mt = 0; mt < 2; mt++)
#pragma unroll
            for (int nt = 0; nt < 8; nt++)
#pragma unroll
                for (int q = 0; q < 4; q++) sacc[mt][nt][q] = 0.f;

        // S = Q @ K^T for this chunk
#pragma unroll
        for (int ks = 0; ks < 4; ks++) {
#pragma unroll
            for (int nt = 0; nt < 8; nt++) {
                int kr = cb + nt * 8 + gid;
                uint32_t bf[2];
                int kb = 16 * ks + 2 * tig;
                bf[0] = *(const uint32_t*)&qk[kr * AQS + kb];
                bf[1] = *(const uint32_t*)&qk[kr * AQS + kb + 8];
                mma_f16(sacc[0][nt], qf[0][ks], bf);
                mma_f16(sacc[1][nt], qf[1][ks], bf);
            }
        }

        // online softmax update (rows: mt x {gid, gid+8})
#pragma unroll
        for (int mt = 0; mt < 2; mt++) {
#pragma unroll
            for (int h = 0; h < 2; h++) {
                float mx = -1e30f;
#pragma unroll
                for (int nt = 0; nt < 8; nt++) {
                    mx = fmaxf(mx, sacc[mt][nt][h * 2]);
                    mx = fmaxf(mx, sacc[mt][nt][h * 2 + 1]);
                }
                mx *= scale;
                mx = fmaxf(mx, __shfl_xor_sync(0xFFFFFFFF, mx, 1));
                mx = fmaxf(mx, __shfl_xor_sync(0xFFFFFFFF, mx, 2));
                float newm = fmaxf(mrow[mt][h], mx);
                float scl  = __expf(mrow[mt][h] - newm);
                float rsum = 0.f;
#pragma unroll
                for (int nt = 0; nt < 8; nt++) {
                    float e0 = __expf(sacc[mt][nt][h * 2] * scale - newm);
                    float e1 = __expf(sacc[mt][nt][h * 2 + 1] * scale - newm);
                    sacc[mt][nt][h * 2]     = e0;
                    sacc[mt][nt][h * 2 + 1] = e1;
                    rsum += e0 + e1;
                }
                rsum += __shfl_xor_sync(0xFFFFFFFF, rsum, 1);
                rsum += __shfl_xor_sync(0xFFFFFFFF, rsum, 2);
                lrow[mt][h] = lrow[mt][h] * scl + rsum;
                mrow[mt][h] = newm;
#pragma unroll
                for (int nt = 0; nt < 8; nt++) {
                    oacc[mt][nt][h * 2]     *= scl;
                    oacc[mt][nt][h * 2 + 1] *= scl;
                }
            }
        }

        // O += P @ V  (P frags from exp'd S regs)
#pragma unroll
        for (int ks = 0; ks < 4; ks++) {
            uint32_t pf[2][4];
#pragma unroll
            for (int mt = 0; mt < 2; mt++) {
                __half2 h0 = __floats2half2_rn(sacc[mt][2 * ks][0],     sacc[mt][2 * ks][1]);
                __half2 h1 = __floats2half2_rn(sacc[mt][2 * ks][2],     sacc[mt][2 * ks][3]);
                __half2 h2 = __floats2half2_rn(sacc[mt][2 * ks + 1][0], sacc[mt][2 * ks + 1][1]);
                __half2 h3 = __floats2half2_rn(sacc[mt][2 * ks + 1][2], sacc[mt][2 * ks + 1][3]);
                pf[mt][0] = *(uint32_t*)&h0;
                pf[mt][1] = *(uint32_t*)&h1;
                pf[mt][2] = *(uint32_t*)&h2;
                pf[mt][3] = *(uint32_t*)&h3;
            }
#pragma unroll
            for (int dnt = 0; dnt < 8; dnt++) {
                int vr = dnt * 8 + gid;
                uint32_t vf[2];
                int kcol = cb + 16 * ks + 2 * tig;
                vf[0] = *(const uint32_t*)&vs[vr * AVS + kcol];
                vf[1] = *(const uint32_t*)&vs[vr * AVS + kcol + 8];
                mma_f16(oacc[0][dnt], pf[0], vf);
                mma_f16(oacc[1][dnt], pf[1], vf);
            }
        }
    }

    // ---- write O: transpose via reused smem, coalesced [d][w] stores ----
    __syncthreads();
    float* obuf = (float*)smraw;      // [64][260]
#pragma unroll
    for (int mt = 0; mt < 2; mt++) {
#pragma unroll
        for (int dnt = 0; dnt < 8; dnt++) {
#pragma unroll
            for (int q = 0; q < 4; q++) {
                int row = warp * 32 + mt * 16 + gid + (q >> 1) * 8;   // local query
                int d   = dnt * 8 + 2 * tig + (q & 1);
                obuf[d * 260 + row] = oacc[mt][dnt][q] / lrow[mt][q >> 1];
            }
        }
    }
    __syncthreads();
    float* ob = o + ((size_t)c * F_DIM + (size_t)hh * D_HEAD) * W_FR + qh * 256;
#pragma unroll
    for (int rep = 0; rep < 2; rep++) {
        int idx = tid + rep * 256;            // d = idx>>8 pairs... iterate d rows
    }
    for (int d = 0; d < 64; d++)
        ob[(size_t)d * W_FR + tid] = obuf[d * 260 + tid];
}

// ---------------------------------------------------------------------------
// Launch
// ---------------------------------------------------------------------------
extern "C" void kernel_launch(void* const* d_in, const int* in_sizes, int n_in,
                              void* d_out, int out_size)
{
    (void)in_sizes; (void)n_in; (void)out_size;
    const float* x  = (const float*)d_in[0];
    const float* g1 = (const float*)d_in[1];
    const float* b1 = (const float*)d_in[2];
    const float* wq = (const float*)d_in[3];
    const float* wo = (const float*)d_in[4];
    const float* fr = (const float*)d_in[5];
    const float* g2 = (const float*)d_in[6];
    const float* b2 = (const float*)d_in[7];
    const float* w1 = (const float*)d_in[8];
    const float* w2 = (const float*)d_in[9];
    float* out = (float*)d_out;

    float *z, *p, *o, *h;
    __half *wqh, *woh, *w1h, *w2h, *t1h, *t2h;
    cudaGetSymbolAddress((void**)&z,   g_z);
    cudaGetSymbolAddress((void**)&p,   g_p);
    cudaGetSymbolAddress((void**)&o,   g_o);
    cudaGetSymbolAddress((void**)&h,   g_h);
    cudaGetSymbolAddress((void**)&wqh, g_wqh);
    cudaGetSymbolAddress((void**)&woh, g_woh);
    cudaGetSymbolAddress((void**)&w1h, g_w1h);
    cudaGetSymbolAddress((void**)&w2h, g_w2h);
    cudaGetSymbolAddress((void**)&t1h, g_t1h);
    cudaGetSymbolAddress((void**)&t2h, g_t2h);

    cudaFuncSetAttribute(fattn_kernel,
                         cudaFuncAttributeMaxDynamicSharedMemorySize, ATT_SMEM);

    const size_t nw  = (size_t)C_CH * F_DIM * F_DIM;
    const size_t nw1 = (size_t)C_CH * F4 * F_DIM;
    dim3 tb(32, 8);

    f2h_kernel<<<(int)(nw  / 4 / 256), 256>>>(wq, wqh, nw);
    f2h_kernel<<<(int)(nw  / 4 / 256), 256>>>(wo, woh, nw);
    f2h_kernel<<<(int)(nw1 / 4 / 256), 256>>>(w1, w1h, nw1);
    f2h_kernel<<<(int)(nw1 / 4 / 256), 256>>>(w2, w2h, nw1);

    frame_norm_kernel<<<dim3(8, 16), 256>>>(x, g1, b1, z);
    tch_kernel<<<dim3(32, 16, 8), tb>>>(z, t1h, F_DIM, W_FR);
    hgemm_kernel<<<dim3(4, 8, 8), 256>>>(wqh, t1h, p, nullptr, F_DIM, F_DIM, 0);
    fattn_kernel<<<256, 256, ATT_SMEM>>>(p, fr, o);
    tch_kernel<<<dim3(32, 16, 8), tb>>>(o, t1h, F_DIM, W_FR);
    hgemm_kernel<<<dim3(4, 8, 8), 256>>>(woh, t1h, out, x, F_DIM, F_DIM, 2);
    frame_norm_kernel<<<dim3(8, 16), 256>>>(out, g2, b2, z);
    tch_kernel<<<dim3(32, 16, 8), tb>>>(z, t1h, F_DIM, W_FR);
    hgemm_kernel<<<dim3(4, 32, 8), 256>>>(w1h, t1h, h, nullptr, F4, F_DIM, 1);
    tch_kernel<<<dim3(128, 16, 8), tb>>>(h, t2h, F4, W_FR);
    hgemm_kernel<<<dim3(4, 8, 8), 256>>>(w2h, t2h, out, out, F_DIM, F4, 2);
}

// round 10
// speedup vs baseline: 2.3091x; 1.1621x over previous
#include <cuda_runtime.h>
#include <cuda_fp16.h>
#include <math.h>
#include <stdint.h>

// Problem constants
#define C_CH 8
#define F_DIM 1024
#define W_FR 512
#define H_HEADS 16
#define D_HEAD 64
#define F4 4096

// ---------------------------------------------------------------------------
// Scratch
// ---------------------------------------------------------------------------
__device__ float g_z[C_CH * F_DIM * W_FR];                        // 16 MB
__device__ float g_p[C_CH * F_DIM * W_FR];                        // 16 MB
__device__ float g_o[C_CH * F_DIM * W_FR];                        // 16 MB
__device__ float g_h[(size_t)C_CH * F4 * W_FR];                   // 64 MB
__device__ __align__(16) __half g_wqh[C_CH * F_DIM * F_DIM];      // 16 MB
__device__ __align__(16) __half g_woh[C_CH * F_DIM * F_DIM];      // 16 MB
__device__ __align__(16) __half g_w1h[(size_t)C_CH * F4 * F_DIM]; // 64 MB
__device__ __align__(16) __half g_w2h[(size_t)C_CH * F_DIM * F4]; // 64 MB
__device__ __align__(16) __half g_t1h[C_CH * W_FR * F_DIM];       // 8 MB
__device__ __align__(16) __half g_t2h[(size_t)C_CH * W_FR * F4];  // 32 MB

// ---------------------------------------------------------------------------
// helpers
// ---------------------------------------------------------------------------
__device__ __forceinline__ uint32_t smem_u32(const void* p) {
    uint32_t a;
    asm("{ .reg .u64 t; cvta.to.shared.u64 t, %1; cvt.u32.u64 %0, t; }" : "=r"(a) : "l"(p));
    return a;
}
__device__ __forceinline__ void cp16(void* dst, const void* src) {
    uint32_t d = (uint32_t)__cvta_generic_to_shared(dst);
    asm volatile("cp.async.ca.shared.global [%0], [%1], 16;" :: "r"(d), "l"(src));
}
__device__ __forceinline__ void cp16s(uint32_t dst, const void* src) {
    asm volatile("cp.async.ca.shared.global [%0], [%1], 16;" :: "r"(dst), "l"(src));
}
__device__ __forceinline__ void mma_f16(float* c, const uint32_t* a, const uint32_t* b) {
    asm volatile(
        "mma.sync.aligned.m16n8k16.row.col.f32.f16.f16.f32 "
        "{%0,%1,%2,%3}, {%4,%5,%6,%7}, {%8,%9}, {%0,%1,%2,%3};"
        : "+f"(c[0]), "+f"(c[1]), "+f"(c[2]), "+f"(c[3])
        : "r"(a[0]), "r"(a[1]), "r"(a[2]), "r"(a[3]), "r"(b[0]), "r"(b[1]));
}
__device__ __forceinline__ void ldsm4(uint32_t* r, uint32_t addr) {
    asm volatile("ldmatrix.sync.aligned.m8n8.x4.shared.b16 {%0,%1,%2,%3}, [%4];"
        : "=r"(r[0]), "=r"(r[1]), "=r"(r[2]), "=r"(r[3]) : "r"(addr));
}

// ---------------------------------------------------------------------------
// fp32 -> fp16 elementwise (weights)
// ---------------------------------------------------------------------------
__global__ __launch_bounds__(256) void f2h_kernel(
    const float* __restrict__ in, __half* __restrict__ out, size_t n)
{
    size_t i = ((size_t)blockIdx.x * blockDim.x + threadIdx.x) * 4;
    if (i >= n) return;
    float4 v = *(const float4*)(in + i);
    *(__half2*)(out + i)     = __floats2half2_rn(v.x, v.y);
    *(__half2*)(out + i + 2) = __floats2half2_rn(v.z, v.w);
}

// ---------------------------------------------------------------------------
// Transpose + convert: out_h[c][n][k] = (half) in[c][k][n]
// ---------------------------------------------------------------------------
__global__ __launch_bounds__(256) void tch_kernel(
    const float* __restrict__ in, __half* __restrict__ out, int K, int N)
{
    __shared__ float t[32][33];
    int c  = blockIdx.z;
    int k0 = blockIdx.x * 32, n0 = blockIdx.y * 32;
    in  += (size_t)c * K * N;
    out += (size_t)c * N * K;
    int tx = threadIdx.x, ty = threadIdx.y;
#pragma unroll
    for (int j = 0; j < 32; j += 8)
        t[ty + j][tx] = in[(size_t)(k0 + ty + j) * N + n0 + tx];
    __syncthreads();
#pragma unroll
    for (int j = 0; j < 32; j += 8)
        out[(size_t)(n0 + ty + j) * K + k0 + tx] = __float2half(t[tx][ty + j]);
}

// ---------------------------------------------------------------------------
// Frame norm (unchanged)
// ---------------------------------------------------------------------------
__global__ __launch_bounds__(256) void frame_norm_kernel(
    const float* __restrict__ in, const float* __restrict__ gw,
    const float* __restrict__ bw, float* __restrict__ out)
{
    int c  = blockIdx.x;
    int w0 = blockIdx.y * 32;
    int wx = threadIdx.x & 31;
    int fg = threadIdx.x >> 5;
    const float* base = in + ((size_t)c * F_DIM) * W_FR + w0 + wx;

    float s = 0.f, ss = 0.f;
    for (int f = fg; f < F_DIM; f += 8) {
        float v = base[(size_t)f * W_FR];
        s += v; ss += v * v;
    }
    __shared__ float red[2][8][32];
    __shared__ float smu[32], srs[32];
    red[0][fg][wx] = s; red[1][fg][wx] = ss;
    __syncthreads();
    if (fg == 0) {
        float S = 0.f, SS = 0.f;
#pragma unroll
        for (int i = 0; i < 8; i++) { S += red[0][i][wx]; SS += red[1][i][wx]; }
        float mu  = S * (1.0f / F_DIM);
        float var = SS * (1.0f / F_DIM) - mu * mu;
        smu[wx] = mu;
        srs[wx] = rsqrtf(var + 1e-5f);
    }
    __syncthreads();
    float mu = smu[wx], rs = srs[wx];
    float* ob = out + ((size_t)c * F_DIM) * W_FR + w0 + wx;
    for (int f = fg; f < F_DIM; f += 8) {
        float v = base[(size_t)f * W_FR];
        ob[(size_t)f * W_FR] = (v - mu) * rs * gw[f] + bw[f];
    }
}

// ---------------------------------------------------------------------------
// FP16 tensor-core batched GEMM v2: ldmatrix + BK=32 + 4-stage cp.async.
// C[c][M,512] = A[c][M,K] x BT[c][512,K], both K-major fp16.
// 256 thr = 8 warps (2m x 4n), warp tile 64x32. Rows padded to 40 halves
// (80 B): LDSM row banks r*20%32 all-distinct. Dynamic smem 80 KB, 2 CTA/SM.
// epi: 0 = store, 1 = exact GELU, 2 = add residual R
// ---------------------------------------------------------------------------
#define BK2 32
#define HP 40
#define NSTG 4
#define HG_MAT (128 * HP)                       // halves per matrix per stage
#define HG_SMEM (NSTG * 2 * HG_MAT * 2)         // 81,920 B

__global__ __launch_bounds__(256, 2) void hgemm_kernel(
    const __half* __restrict__ A, const __half* __restrict__ BT,
    float* __restrict__ Cm, const float* __restrict__ R,
    int M, int K, int epi)
{
    const int N = W_FR;
    int c  = blockIdx.z;
    int bm = blockIdx.y * 128;
    int bn = blockIdx.x * 128;
    A  += (size_t)c * M * K;
    BT += (size_t)c * N * K;
    Cm += (size_t)c * M * N;
    if (R) R += (size_t)c * M * N;

    extern __shared__ __align__(16) __half hsm[];
    uint32_t smb = smem_u32(hsm);

    int tid  = threadIdx.x;
    int warp = tid >> 5;
    int lane = tid & 31;
    int gid  = lane >> 2;
    int tig  = lane & 3;
    int wm   = warp >> 2;
    int wn   = warp & 3;

    // copy assignment: row = tid>>1, col halves = (tid&1)*16, two cp16 each mat
    int cr = tid >> 1;
    int cc = (tid & 1) * 16;
    const __half* Ag = A  + (size_t)(bm + cr) * K + cc;
    const __half* Bg = BT + (size_t)(bn + cr) * K + cc;
    uint32_t sdst = (uint32_t)(cr * HP + cc) * 2;   // byte offset within matrix

    // ldmatrix per-lane offsets (halves)
    int lr = lane & 7;
    int lm = (lane >> 3) & 1;
    int lc = (lane >> 4) & 1;
    uint32_t aoff = (uint32_t)((wm * 64 + lr + lm * 8) * HP + lc * 8) * 2;
    uint32_t boff = (uint32_t)((wn * 32 + lr + lc * 8) * HP + lm * 8) * 2;

    const int NT = K / BK2;

    // prologue: stages 0..2
#pragma unroll
    for (int t = 0; t < NSTG - 1; t++) {
        uint32_t sA = smb + (uint32_t)(t * 2 * HG_MAT) * 2;
        uint32_t sB = sA + HG_MAT * 2;
        cp16s(sA + sdst,      Ag + (size_t)t * BK2);
        cp16s(sA + sdst + 16, Ag + (size_t)t * BK2 + 8);
        cp16s(sB + sdst,      Bg + (size_t)t * BK2);
        cp16s(sB + sdst + 16, Bg + (size_t)t * BK2 + 8);
        asm volatile("cp.async.commit_group;");
    }

    float acc[4][4][4];
#pragma unroll
    for (int i = 0; i < 4; i++)
#pragma unroll
        for (int j = 0; j < 4; j++)
#pragma unroll
            for (int q = 0; q < 4; q++) acc[i][j][q] = 0.f;

    for (int t = 0; t < NT; t++) {
        uint32_t sA = smb + (uint32_t)((t % NSTG) * 2 * HG_MAT) * 2;
        uint32_t sB = sA + HG_MAT * 2;
        asm volatile("cp.async.wait_group %0;" :: "n"(NSTG - 2));
        __syncthreads();

#pragma unroll
        for (int s = 0; s < 2; s++) {
            uint32_t bf[2][4];
            ldsm4(bf[0], sB + boff + (0 * 16 * HP + s * 16) * 2);
            ldsm4(bf[1], sB + boff + (1 * 16 * HP + s * 16) * 2);
#pragma unroll
            for (int mt = 0; mt < 4; mt++) {
                uint32_t af[4];
                ldsm4(af, sA + aoff + (mt * 16 * HP + s * 16) * 2);
                mma_f16(acc[mt][0], af, &bf[0][0]);
                mma_f16(acc[mt][1], af, &bf[0][2]);
                mma_f16(acc[mt][2], af, &bf[1][0]);
                mma_f16(acc[mt][3], af, &bf[1][2]);
            }
        }

        // issue tile t+3 into stage (t+3)%NSTG (= (t-1)%NSTG, drained)
        if (t + NSTG - 1 < NT) {
            int tn = t + NSTG - 1;
            uint32_t dA = smb + (uint32_t)((tn % NSTG) * 2 * HG_MAT) * 2;
            uint32_t dB = dA + HG_MAT * 2;
            cp16s(dA + sdst,      Ag + (size_t)tn * BK2);
            cp16s(dA + sdst + 16, Ag + (size_t)tn * BK2 + 8);
            cp16s(dB + sdst,      Bg + (size_t)tn * BK2);
            cp16s(dB + sdst + 16, Bg + (size_t)tn * BK2 + 8);
        }
        asm volatile("cp.async.commit_group;");
    }

    // epilogue
#pragma unroll
    for (int mt = 0; mt < 4; mt++) {
#pragma unroll
        for (int nt = 0; nt < 4; nt++) {
            int row0 = bm + wm * 64 + mt * 16 + gid;
            int col  = bn + wn * 32 + nt * 8 + 2 * tig;
#pragma unroll
            for (int half = 0; half < 2; half++) {
                int row = row0 + half * 8;
                float2 v = make_float2(acc[mt][nt][half * 2], acc[mt][nt][half * 2 + 1]);
                size_t off = (size_t)row * N + col;
                if (epi == 1) {
                    v.x = 0.5f * v.x * (1.f + erff(v.x * 0.70710678118654752f));
                    v.y = 0.5f * v.y * (1.f + erff(v.y * 0.70710678118654752f));
                } else if (epi == 2) {
                    float2 rv = *(const float2*)(R + off);
                    v.x += rv.x; v.y += rv.y;
                }
                *(float2*)(Cm + off) = v;
            }
        }
    }
}

// ---------------------------------------------------------------------------
// Flash attention, fp16 mma (unchanged logic from R9; dead code removed)
// ---------------------------------------------------------------------------
#define AQS 72
#define AVS 520
#define ATT_SMEM (512 * AQS * 2 + 64 * AVS * 2)   // 140,288 B

__global__ __launch_bounds__(256) void fattn_kernel(
    const float* __restrict__ p, const float* __restrict__ freqs,
    float* __restrict__ o)
{
    extern __shared__ __align__(16) char smraw[];
    __half* qk = (__half*)smraw;
    __half* vs = (__half*)(smraw + 512 * AQS * 2);

    int head = blockIdx.x >> 1;
    int qh   = blockIdx.x & 1;
    int c  = head >> 4;
    int hh = head & 15;
    const float* slab = p + ((size_t)c * F_DIM + (size_t)hh * D_HEAD) * W_FR;

    int tid = threadIdx.x;

#pragma unroll
    for (int rep = 0; rep < 2; rep++) {
        int w = tid + rep * 256;
        float fw = (float)w;
#pragma unroll
        for (int i = 0; i < 16; i++) {
            float e0 = slab[(size_t)(2 * i) * W_FR + w];
            float e1 = slab[(size_t)(2 * i + 1) * W_FR + w];
            float si, co;
            sincosf(fw * freqs[i], &si, &co);
            qk[w * AQS + 2 * i]     = __float2half(e0 * co - e1 * si);
            qk[w * AQS + 2 * i + 1] = __float2half(e1 * co + e0 * si);
            vs[(2 * i) * AVS + w]     = __float2half(e0);
            vs[(2 * i + 1) * AVS + w] = __float2half(e1);
        }
#pragma unroll
        for (int d = 32; d < 64; d++) {
            __half he = __float2half(slab[(size_t)d * W_FR + w]);
            qk[w * AQS + d] = he;
            vs[d * AVS + w] = he;
        }
    }
    __syncthreads();

    int warp = tid >> 5, lane = tid & 31, gid = lane >> 2, tig = lane & 3;
    int q0 = qh * 256 + warp * 32;
    const float scale = 0.03125f;

    uint32_t qf[2][4][4];
#pragma unroll
    for (int mt = 0; mt < 2; mt++) {
        int qr = q0 + mt * 16 + gid;
#pragma unroll
        for (int ks = 0; ks < 4; ks++) {
            int kb = 16 * ks + 2 * tig;
            qf[mt][ks][0] = *(const uint32_t*)&qk[qr * AQS + kb];
            qf[mt][ks][1] = *(const uint32_t*)&qk[(qr + 8) * AQS + kb];
            qf[mt][ks][2] = *(const uint32_t*)&qk[qr * AQS + kb + 8];
            qf[mt][ks][3] = *(const uint32_t*)&qk[(qr + 8) * AQS + kb + 8];
        }
    }

    float oacc[2][8][4];
#pragma unroll
    for (int mt = 0; mt < 2; mt++)
#pragma unroll
        for (int nt = 0; nt < 8; nt++)
#pragma unroll
            for (int q = 0; q < 4; q++) oacc[mt][nt][q] = 0.f;
    float mrow[2][2] = { {-1e30f, -1e30f}, {-1e30f, -1e30f} };
    float lrow[2][2] = { {0.f, 0.f}, {0.f, 0.f} };

    for (int ch = 0; ch < 8; ch++) {
        int cb = ch * 64;
        float sacc[2][8][4];
#pragma unroll
        for (int mt = 0; mt < 2; mt++)
#pragma unroll
            for (int nt = 0; nt < 8; nt++)
#pragma unroll
                for (int q = 0; q < 4; q++) sacc[mt][nt][q] = 0.f;

#pragma unroll
        for (int ks = 0; ks < 4; ks++) {
#pragma unroll
            for (int nt = 0; nt < 8; nt++) {
                int kr = cb + nt * 8 + gid;
                uint32_t bf[2];
                int kb = 16 * ks + 2 * tig;
                bf[0] = *(const uint32_t*)&qk[kr * AQS + kb];
                bf[1] = *(const uint32_t*)&qk[kr * AQS + kb + 8];
                mma_f16(sacc[0][nt], qf[0][ks], bf);
                mma_f16(sacc[1][nt], qf[1][ks], bf);
            }
        }

#pragma unroll
        for (int mt = 0; mt < 2; mt++) {
#pragma unroll
            for (int h = 0; h < 2; h++) {
                float mx = -1e30f;
#pragma unroll
                for (int nt = 0; nt < 8; nt++) {
                    mx = fmaxf(mx, sacc[mt][nt][h * 2]);
                    mx = fmaxf(mx, sacc[mt][nt][h * 2 + 1]);
                }
                mx *= scale;
                mx = fmaxf(mx, __shfl_xor_sync(0xFFFFFFFF, mx, 1));
                mx = fmaxf(mx, __shfl_xor_sync(0xFFFFFFFF, mx, 2));
                float newm = fmaxf(mrow[mt][h], mx);
                float scl  = __expf(mrow[mt][h] - newm);
                float rsum = 0.f;
#pragma unroll
                for (int nt = 0; nt < 8; nt++) {
                    float e0 = __expf(sacc[mt][nt][h * 2] * scale - newm);
                    float e1 = __expf(sacc[mt][nt][h * 2 + 1] * scale - newm);
                    sacc[mt][nt][h * 2]     = e0;
                    sacc[mt][nt][h * 2 + 1] = e1;
                    rsum += e0 + e1;
                }
                rsum += __shfl_xor_sync(0xFFFFFFFF, rsum, 1);
                rsum += __shfl_xor_sync(0xFFFFFFFF, rsum, 2);
                lrow[mt][h] = lrow[mt][h] * scl + rsum;
                mrow[mt][h] = newm;
#pragma unroll
                for (int nt = 0; nt < 8; nt++) {
                    oacc[mt][nt][h * 2]     *= scl;
                    oacc[mt][nt][h * 2 + 1] *= scl;
                }
            }
        }

#pragma unroll
        for (int ks = 0; ks < 4; ks++) {
            uint32_t pf[2][4];
#pragma unroll
            for (int mt = 0; mt < 2; mt++) {
                __half2 h0 = __floats2half2_rn(sacc[mt][2 * ks][0],     sacc[mt][2 * ks][1]);
                __half2 h1 = __floats2half2_rn(sacc[mt][2 * ks][2],     sacc[mt][2 * ks][3]);
                __half2 h2 = __floats2half2_rn(sacc[mt][2 * ks + 1][0], sacc[mt][2 * ks + 1][1]);
                __half2 h3 = __floats2half2_rn(sacc[mt][2 * ks + 1][2], sacc[mt][2 * ks + 1][3]);
                pf[mt][0] = *(uint32_t*)&h0;
                pf[mt][1] = *(uint32_t*)&h1;
                pf[mt][2] = *(uint32_t*)&h2;
                pf[mt][3] = *(uint32_t*)&h3;
            }
#pragma unroll
            for (int dnt = 0; dnt < 8; dnt++) {
                int vr = dnt * 8 + gid;
                uint32_t vf[2];
                int kcol = cb + 16 * ks + 2 * tig;
                vf[0] = *(const uint32_t*)&vs[vr * AVS + kcol];
                vf[1] = *(const uint32_t*)&vs[vr * AVS + kcol + 8];
                mma_f16(oacc[0][dnt], pf[0], vf);
                mma_f16(oacc[1][dnt], pf[1], vf);
            }
        }
    }

    __syncthreads();
    float* obuf = (float*)smraw;      // [64][260]
#pragma unroll
    for (int mt = 0; mt < 2; mt++) {
#pragma unroll
        for (int dnt = 0; dnt < 8; dnt++) {
#pragma unroll
            for (int q = 0; q < 4; q++) {
                int row = warp * 32 + mt * 16 + gid + (q >> 1) * 8;
                int d   = dnt * 8 + 2 * tig + (q & 1);
                obuf[d * 260 + row] = oacc[mt][dnt][q] / lrow[mt][q >> 1];
            }
        }
    }
    __syncthreads();
    float* ob = o + ((size_t)c * F_DIM + (size_t)hh * D_HEAD) * W_FR + qh * 256;
    for (int d = 0; d < 64; d++)
        ob[(size_t)d * W_FR + tid] = obuf[d * 260 + tid];
}

// ---------------------------------------------------------------------------
// Launch
// ---------------------------------------------------------------------------
extern "C" void kernel_launch(void* const* d_in, const int* in_sizes, int n_in,
                              void* d_out, int out_size)
{
    (void)in_sizes; (void)n_in; (void)out_size;
    const float* x  = (const float*)d_in[0];
    const float* g1 = (const float*)d_in[1];
    const float* b1 = (const float*)d_in[2];
    const float* wq = (const float*)d_in[3];
    const float* wo = (const float*)d_in[4];
    const float* fr = (const float*)d_in[5];
    const float* g2 = (const float*)d_in[6];
    const float* b2 = (const float*)d_in[7];
    const float* w1 = (const float*)d_in[8];
    const float* w2 = (const float*)d_in[9];
    float* out = (float*)d_out;

    float *z, *p, *o, *h;
    __half *wqh, *woh, *w1h, *w2h, *t1h, *t2h;
    cudaGetSymbolAddress((void**)&z,   g_z);
    cudaGetSymbolAddress((void**)&p,   g_p);
    cudaGetSymbolAddress((void**)&o,   g_o);
    cudaGetSymbolAddress((void**)&h,   g_h);
    cudaGetSymbolAddress((void**)&wqh, g_wqh);
    cudaGetSymbolAddress((void**)&woh, g_woh);
    cudaGetSymbolAddress((void**)&w1h, g_w1h);
    cudaGetSymbolAddress((void**)&w2h, g_w2h);
    cudaGetSymbolAddress((void**)&t1h, g_t1h);
    cudaGetSymbolAddress((void**)&t2h, g_t2h);

    cudaFuncSetAttribute(fattn_kernel,
                         cudaFuncAttributeMaxDynamicSharedMemorySize, ATT_SMEM);
    cudaFuncSetAttribute(hgemm_kernel,
                         cudaFuncAttributeMaxDynamicSharedMemorySize, HG_SMEM);

    const size_t nw  = (size_t)C_CH * F_DIM * F_DIM;
    const size_t nw1 = (size_t)C_CH * F4 * F_DIM;
    dim3 tb(32, 8);

    f2h_kernel<<<(int)(nw  / 4 / 256), 256>>>(wq, wqh, nw);
    f2h_kernel<<<(int)(nw  / 4 / 256), 256>>>(wo, woh, nw);
    f2h_kernel<<<(int)(nw1 / 4 / 256), 256>>>(w1, w1h, nw1);
    f2h_kernel<<<(int)(nw1 / 4 / 256), 256>>>(w2, w2h, nw1);

    frame_norm_kernel<<<dim3(8, 16), 256>>>(x, g1, b1, z);
    tch_kernel<<<dim3(32, 16, 8), tb>>>(z, t1h, F_DIM, W_FR);
    hgemm_kernel<<<dim3(4, 8, 8), 256, HG_SMEM>>>(wqh, t1h, p, nullptr, F_DIM, F_DIM, 0);
    fattn_kernel<<<256, 256, ATT_SMEM>>>(p, fr, o);
    tch_kernel<<<dim3(32, 16, 8), tb>>>(o, t1h, F_DIM, W_FR);
    hgemm_kernel<<<dim3(4, 8, 8), 256, HG_SMEM>>>(woh, t1h, out, x, F_DIM, F_DIM, 2);
    frame_norm_kernel<<<dim3(8, 16), 256>>>(out, g2, b2, z);
    tch_kernel<<<dim3(32, 16, 8), tb>>>(z, t1h, F_DIM, W_FR);
    hgemm_kernel<<<dim3(4, 32, 8), 256, HG_SMEM>>>(w1h, t1h, h, nullptr, F4, F_DIM, 1);
    tch_kernel<<<dim3(128, 16, 8), tb>>>(h, t2h, F4, W_FR);
    hgemm_kernel<<<dim3(4, 8, 8), 256, HG_SMEM>>>(w2h, t2h, out, out, F_DIM, F4, 2);
}